// round 1
// baseline (speedup 1.0000x reference)
#include <cuda_runtime.h>
#include <cuda_bf16.h>
#include <cstdint>
#include <cstddef>

// ---------------------------------------------------------------------------
// SingleStreamBlock: B=2, L=2048, H=2048, NH=16, D=128, MLP=8192
// ---------------------------------------------------------------------------
#define BB   2
#define LL   2048
#define HH   2048
#define NHH  16
#define DD   128
#define MLPD 8192
#define H3   6144          // 3*H
#define HC1  14336         // 3*H + MLP  (lin1 out cols)
#define HC2  10240         // H + MLP    (lin2 in cols)

// ------------------------- scratch (device globals) ------------------------
__device__ float g_mod   [BB * H3];                       // shift|scale|gate
__device__ float g_xmod  [(size_t)BB * LL * HH];          // 33.5 MB
__device__ float g_h     [(size_t)BB * LL * HC1];         // 235 MB
__device__ float g_q     [(size_t)BB * NHH * LL * DD];    // 33.5 MB
__device__ float g_k     [(size_t)BB * NHH * LL * DD];    // 33.5 MB
__device__ float g_logits[(size_t)BB * NHH * LL * LL];    // 537 MB
__device__ float g_cat   [(size_t)BB * LL * HC2];         // 167 MB (attn|gelu)

// ------------------------------ helpers ------------------------------------
__device__ __forceinline__ unsigned f2tf(float x) {
    unsigned r;
    asm("cvt.rna.tf32.f32 %0, %1;" : "=r"(r) : "f"(x));
    return r;
}

__device__ __forceinline__ void mma8(float* d, const unsigned* a, const unsigned* b) {
    asm volatile(
        "mma.sync.aligned.m16n8k8.row.col.f32.tf32.tf32.f32 "
        "{%0,%1,%2,%3}, {%4,%5,%6,%7}, {%8,%9}, {%0,%1,%2,%3};\n"
        : "+f"(d[0]), "+f"(d[1]), "+f"(d[2]), "+f"(d[3])
        : "r"(a[0]), "r"(a[1]), "r"(a[2]), "r"(a[3]), "r"(b[0]), "r"(b[1]));
}

// ------------------------- K0: mod = silu(vec) @ mod_w^T + mod_b ------------
__global__ void mod_gemm_kernel(const float* __restrict__ vec,
                                const float* __restrict__ mod_w,
                                const float* __restrict__ mod_b) {
    int w    = (blockIdx.x * blockDim.x + threadIdx.x) >> 5;   // global warp
    int lane = threadIdx.x & 31;
    if (w >= BB * H3) return;
    int b = w / H3, j = w % H3;
    const float* vr = vec + (size_t)b * HH;
    const float* wr = mod_w + (size_t)j * HH;
    float acc = 0.f;
    for (int k = lane; k < HH; k += 32) {
        float v = vr[k];
        float s = v / (1.f + expf(-v));
        acc += s * wr[k];
    }
#pragma unroll
    for (int o = 16; o; o >>= 1) acc += __shfl_xor_sync(0xffffffffu, acc, o);
    if (lane == 0) g_mod[w] = acc + mod_b[j];
}

// ------------------ K1: x_mod = (1+scale)*LN(x) + shift ---------------------
__global__ void ln_mod_kernel(const float* __restrict__ x) {
    __shared__ float red[32];
    __shared__ float bval[2];
    int row = blockIdx.x;                 // 0..4095
    int tid = threadIdx.x;                // 256 threads
    int lane = tid & 31, wid = tid >> 5;
    const float* xr = x + (size_t)row * HH;

    float v[8];
    float s = 0.f;
#pragma unroll
    for (int i = 0; i < 8; i++) { v[i] = xr[tid + i * 256]; s += v[i]; }
#pragma unroll
    for (int o = 16; o; o >>= 1) s += __shfl_xor_sync(0xffffffffu, s, o);
    if (lane == 0) red[wid] = s;
    __syncthreads();
    if (tid < 32) {
        float r = (tid < 8) ? red[tid] : 0.f;
#pragma unroll
        for (int o = 4; o; o >>= 1) r += __shfl_xor_sync(0xffffffffu, r, o);
        if (tid == 0) bval[0] = r;
    }
    __syncthreads();
    float mu = bval[0] * (1.f / HH);

    float sq = 0.f;
#pragma unroll
    for (int i = 0; i < 8; i++) { float d = v[i] - mu; sq += d * d; }
#pragma unroll
    for (int o = 16; o; o >>= 1) sq += __shfl_xor_sync(0xffffffffu, sq, o);
    __syncthreads();
    if (lane == 0) red[wid] = sq;
    __syncthreads();
    if (tid < 32) {
        float r = (tid < 8) ? red[tid] : 0.f;
#pragma unroll
        for (int o = 4; o; o >>= 1) r += __shfl_xor_sync(0xffffffffu, r, o);
        if (tid == 0) bval[1] = r;
    }
    __syncthreads();
    float rstd = rsqrtf(bval[1] * (1.f / HH) + 1e-6f);

    int b = row >> 11;    // row / L
#pragma unroll
    for (int i = 0; i < 8; i++) {
        int c = tid + i * 256;
        float sc = g_mod[b * H3 + HH + c];     // scale
        float sh = g_mod[b * H3 + c];          // shift
        g_xmod[(size_t)row * HH + c] = (1.f + sc) * ((v[i] - mu) * rstd) + sh;
    }
}

// ----------------- K3: q/k rmsnorm + rope -> g_q, g_k -----------------------
__global__ void qkprep_kernel(const float* __restrict__ pe,
                              const float* __restrict__ qsc,
                              const float* __restrict__ ksc) {
    int sel  = blockIdx.y;                                   // 0=q, 1=k
    int gw   = blockIdx.x * (blockDim.x >> 5) + (threadIdx.x >> 5);
    int lane = threadIdx.x & 31;
    // gw in [0, B*NH*L)
    int b   = gw >> 15;            // / (NH*L) = /32768
    int rem = gw & 32767;
    int n   = rem >> 11;           // / L
    int l   = rem & 2047;

    const float* src = g_h + (size_t)(b * LL + l) * HC1 + sel * HH + n * DD;
    float4 t = *(const float4*)(src + lane * 4);
    const float* scp = sel ? ksc : qsc;
    float4 s = *(const float4*)(scp + lane * 4);

    float ss = t.x * t.x + t.y * t.y + t.z * t.z + t.w * t.w;
#pragma unroll
    for (int o = 16; o; o >>= 1) ss += __shfl_xor_sync(0xffffffffu, ss, o);
    float r = rsqrtf(ss * (1.f / DD) + 1e-6f);

    float tx = t.x * r * s.x, ty = t.y * r * s.y;
    float tz = t.z * r * s.z, tw = t.w * r * s.w;

    // pairs i0 = 2*lane, i1 = 2*lane+1 ; pe[b,0,l,i,j,s]
    const float* peb = pe + ((size_t)(b * LL + l) * (DD / 2) + lane * 2) * 4;
    float4 p0 = *(const float4*)(peb);       // (i0: j0s0, j0s1, j1s0, j1s1)
    float4 p1 = *(const float4*)(peb + 4);   // (i1: ...)
    float o0 = p0.x * tx + p0.y * ty;
    float o1 = p0.z * tx + p0.w * ty;
    float o2 = p1.x * tz + p1.y * tw;
    float o3 = p1.z * tz + p1.w * tw;

    float* dst = (sel ? g_k : g_q) + ((size_t)(b * NHH + n) * LL + l) * DD + lane * 4;
    *(float4*)dst = make_float4(o0, o1, o2, o3);
}

// ---------------- K3b: g_cat[:,H:] = gelu(g_h[:,3H:]) -----------------------
__global__ void gelu_kernel() {
    size_t i = (size_t)blockIdx.x * blockDim.x + threadIdx.x;  // B*L*MLP elems
    size_t m = i >> 13;          // / 8192
    size_t j = i & 8191;
    float v = g_h[m * HC1 + H3 + j];
    float t = 0.7978845608028654f * (v + 0.044715f * v * v * v);
    g_cat[m * HC2 + HH + j] = 0.5f * v * (1.f + tanhf(t));
}

// ---------------------- K5: row softmax over g_logits -----------------------
__global__ void softmax_kernel() {
    __shared__ float red[32];
    __shared__ float bval;
    size_t row = blockIdx.x;                   // B*NH*L rows of length L
    float* p = g_logits + row * LL;
    int tid = threadIdx.x, lane = tid & 31, wid = tid >> 5;

    float v[8];
    float mx = -1e30f;
#pragma unroll
    for (int i = 0; i < 8; i++) { v[i] = p[tid + i * 256]; mx = fmaxf(mx, v[i]); }
#pragma unroll
    for (int o = 16; o; o >>= 1) mx = fmaxf(mx, __shfl_xor_sync(0xffffffffu, mx, o));
    if (lane == 0) red[wid] = mx;
    __syncthreads();
    if (tid < 32) {
        float r = (tid < 8) ? red[tid] : -1e30f;
#pragma unroll
        for (int o = 4; o; o >>= 1) r = fmaxf(r, __shfl_xor_sync(0xffffffffu, r, o));
        if (tid == 0) bval = r;
    }
    __syncthreads();
    mx = bval;

    float s = 0.f;
#pragma unroll
    for (int i = 0; i < 8; i++) { v[i] = expf(v[i] - mx); s += v[i]; }
#pragma unroll
    for (int o = 16; o; o >>= 1) s += __shfl_xor_sync(0xffffffffu, s, o);
    __syncthreads();
    if (lane == 0) red[wid] = s;
    __syncthreads();
    if (tid < 32) {
        float r = (tid < 8) ? red[tid] : 0.f;
#pragma unroll
        for (int o = 4; o; o >>= 1) r += __shfl_xor_sync(0xffffffffu, r, o);
        if (tid == 0) bval = r;
    }
    __syncthreads();
    float inv = 1.f / bval;
#pragma unroll
    for (int i = 0; i < 8; i++) p[tid + i * 256] = v[i] * inv;
}

// ------------------------- generic tf32 GEMM --------------------------------
// C[M,N] = A @ op(B) (+epilogue).  A row-major [M,K].
// BLAY 0: B row-major [N,K] (NT).  BLAY 1: B row-major [K,N] (NN).
// EPI  0: store   1: +bias[c]   2: *scl   3: out = x + gate*(v + bias)
#define BM 128
#define BN 128
#define BK 32
#define SPAD 133

template<int EPI>
__device__ __forceinline__ void epi_store(float* __restrict__ C, int ldc,
                                          int r, int c, float v,
                                          const float* __restrict__ bias,
                                          float scl,
                                          const float* __restrict__ xres) {
    if (EPI == 0) {
        C[(size_t)r * ldc + c] = v;
    } else if (EPI == 1) {
        C[(size_t)r * ldc + c] = v + bias[c];
    } else if (EPI == 2) {
        C[(size_t)r * ldc + c] = v * scl;
    } else {
        float g = g_mod[(r >> 11) * H3 + 2 * HH + c];   // gate
        C[(size_t)r * ldc + c] = xres[(size_t)r * ldc + c] + g * (v + bias[c]);
    }
}

template<int BLAY, int EPI>
__global__ __launch_bounds__(256, 2) void gemm_tf32(
    const float* __restrict__ A, int lda, long long Ao, long long Ai,
    const float* __restrict__ B, int ldb, long long Bo, long long Bi,
    float* __restrict__ C, int ldc, long long Co, long long Ci,
    int M, int N, int K, int zdiv,
    const float* __restrict__ bias, float scl,
    const float* __restrict__ xres)
{
    __shared__ unsigned As[BK][SPAD];
    __shared__ unsigned Bs[BK][SPAD];

    int z = blockIdx.z;
    A += (size_t)(z / zdiv) * Ao + (size_t)(z % zdiv) * Ai;
    B += (size_t)(z / zdiv) * Bo + (size_t)(z % zdiv) * Bi;
    C += (size_t)(z / zdiv) * Co + (size_t)(z % zdiv) * Ci;

    int m0 = blockIdx.y * BM;
    int n0 = blockIdx.x * BN;
    int tid = threadIdx.x, lane = tid & 31, w = tid >> 5;
    int wm = w >> 1, wn = w & 1;       // 4x2 warp grid, warp tile 32x64

    float acc[2][8][4];
#pragma unroll
    for (int mi = 0; mi < 2; mi++)
#pragma unroll
        for (int ni = 0; ni < 8; ni++)
#pragma unroll
            for (int e = 0; e < 4; e++) acc[mi][ni][e] = 0.f;

    int nkt = K / BK;
    for (int kt = 0; kt < nkt; ++kt) {
        // ---- stage A tile (always NT: As[k][m]) ----
#pragma unroll
        for (int i = 0; i < 4; i++) {
            int idx = tid + i * 256;              // 0..1023
            int row = idx >> 3;                   // m in tile
            int kq  = (idx & 7) * 4;
            const float4 va = *(const float4*)(A + (size_t)(m0 + row) * lda + kt * BK + kq);
            As[kq + 0][row] = f2tf(va.x);
            As[kq + 1][row] = f2tf(va.y);
            As[kq + 2][row] = f2tf(va.z);
            As[kq + 3][row] = f2tf(va.w);
        }
        // ---- stage B tile (Bs[k][n]) ----
        if (BLAY == 0) {
#pragma unroll
            for (int i = 0; i < 4; i++) {
                int idx = tid + i * 256;
                int row = idx >> 3;               // n in tile
                int kq  = (idx & 7) * 4;
                const float4 vb = *(const float4*)(B + (size_t)(n0 + row) * ldb + kt * BK + kq);
                Bs[kq + 0][row] = f2tf(vb.x);
                Bs[kq + 1][row] = f2tf(vb.y);
                Bs[kq + 2][row] = f2tf(vb.z);
                Bs[kq + 3][row] = f2tf(vb.w);
            }
        } else {
#pragma unroll
            for (int i = 0; i < 4; i++) {
                int idx = tid + i * 256;
                int k  = idx >> 5;                // 0..31
                int nq = (idx & 31) * 4;
                const float4 vb = *(const float4*)(B + (size_t)(kt * BK + k) * ldb + n0 + nq);
                Bs[k][nq + 0] = f2tf(vb.x);
                Bs[k][nq + 1] = f2tf(vb.y);
                Bs[k][nq + 2] = f2tf(vb.z);
                Bs[k][nq + 3] = f2tf(vb.w);
            }
        }
        __syncthreads();

        // ---- compute ----
        const int r0 = lane >> 2, c0 = lane & 3;
#pragma unroll
        for (int ks = 0; ks < 4; ++ks) {
            unsigned af[2][4];
            unsigned bf[8][2];
#pragma unroll
            for (int mi = 0; mi < 2; mi++) {
                int mr = wm * 32 + mi * 16 + r0;
                af[mi][0] = As[ks * 8 + c0][mr];
                af[mi][1] = As[ks * 8 + c0][mr + 8];
                af[mi][2] = As[ks * 8 + c0 + 4][mr];
                af[mi][3] = As[ks * 8 + c0 + 4][mr + 8];
            }
#pragma unroll
            for (int ni = 0; ni < 8; ni++) {
                int nc = wn * 64 + ni * 8 + r0;
                bf[ni][0] = Bs[ks * 8 + c0][nc];
                bf[ni][1] = Bs[ks * 8 + c0 + 4][nc];
            }
#pragma unroll
            for (int mi = 0; mi < 2; mi++)
#pragma unroll
                for (int ni = 0; ni < 8; ni++)
                    mma8(acc[mi][ni], af[mi], bf[ni]);
        }
        __syncthreads();
    }

    // ---- epilogue ----
    int rb = m0 + wm * 32, nb = n0 + wn * 64;
#pragma unroll
    for (int mi = 0; mi < 2; mi++) {
#pragma unroll
        for (int ni = 0; ni < 8; ni++) {
            int r = rb + mi * 16 + (lane >> 2);
            int c = nb + ni * 8 + (lane & 3) * 2;
            epi_store<EPI>(C, ldc, r,     c,     acc[mi][ni][0], bias, scl, xres);
            epi_store<EPI>(C, ldc, r,     c + 1, acc[mi][ni][1], bias, scl, xres);
            epi_store<EPI>(C, ldc, r + 8, c,     acc[mi][ni][2], bias, scl, xres);
            epi_store<EPI>(C, ldc, r + 8, c + 1, acc[mi][ni][3], bias, scl, xres);
        }
    }
}

// ---------------------------------------------------------------------------
extern "C" void kernel_launch(void* const* d_in, const int* in_sizes, int n_in,
                              void* d_out, int out_size) {
    const float* x       = (const float*)d_in[0];
    const float* vec     = (const float*)d_in[1];
    const float* pe      = (const float*)d_in[2];
    const float* mod_w   = (const float*)d_in[3];
    const float* mod_b   = (const float*)d_in[4];
    const float* lin1_w  = (const float*)d_in[5];
    const float* lin1_b  = (const float*)d_in[6];
    const float* lin2_w  = (const float*)d_in[7];
    const float* lin2_b  = (const float*)d_in[8];
    const float* q_scale = (const float*)d_in[9];
    const float* k_scale = (const float*)d_in[10];
    float* out = (float*)d_out;

    void* tmp;
    cudaGetSymbolAddress(&tmp, g_xmod);   float* p_xmod   = (float*)tmp;
    cudaGetSymbolAddress(&tmp, g_h);      float* p_h      = (float*)tmp;
    cudaGetSymbolAddress(&tmp, g_q);      float* p_q      = (float*)tmp;
    cudaGetSymbolAddress(&tmp, g_k);      float* p_k      = (float*)tmp;
    cudaGetSymbolAddress(&tmp, g_logits); float* p_logits = (float*)tmp;
    cudaGetSymbolAddress(&tmp, g_cat);    float* p_cat    = (float*)tmp;

    // K0: modulation vectors
    mod_gemm_kernel<<<(BB * H3) / 8, 256>>>(vec, mod_w, mod_b);
    // K1: layernorm + modulate
    ln_mod_kernel<<<BB * LL, 256>>>(x);
    // K2: h = x_mod @ lin1_w^T + lin1_b          [4096 x 14336], K=2048
    gemm_tf32<0, 1><<<dim3(HC1 / BN, (BB * LL) / BM, 1), 256>>>(
        p_xmod, HH, 0, 0, lin1_w, HH, 0, 0, p_h, HC1, 0, 0,
        BB * LL, HC1, HH, 1, lin1_b, 0.f, nullptr);
    // K3: q/k rmsnorm + rope
    qkprep_kernel<<<dim3((BB * NHH * LL) / 8, 2, 1), 256>>>(pe, q_scale, k_scale);
    // K3b: gelu(mlp) -> g_cat right half
    gelu_kernel<<<(unsigned)(((size_t)BB * LL * MLPD) / 256), 256>>>();
    // K4: logits = q @ k^T / sqrt(D)  batched z = B*NH   [2048 x 2048], K=128
    gemm_tf32<0, 2><<<dim3(LL / BN, LL / BM, BB * NHH), 256>>>(
        p_q, DD, 0, (long long)LL * DD,
        p_k, DD, 0, (long long)LL * DD,
        p_logits, LL, 0, (long long)LL * LL,
        LL, LL, DD, BB * NHH, nullptr, 0.08838834764831845f, nullptr);
    // K5: softmax rows
    softmax_kernel<<<BB * NHH * LL, 256>>>();
    // K6: attn = P @ V   batched  [2048 x 128], K=2048  (V strided inside g_h)
    gemm_tf32<1, 0><<<dim3(1, LL / BM, BB * NHH), 256>>>(
        p_logits, LL, (long long)NHH * LL * LL, (long long)LL * LL,
        p_h + 2 * HH, HC1, (long long)LL * HC1, (long long)DD,
        p_cat, HC2, (long long)LL * HC2, (long long)DD,
        LL, DD, LL, NHH, nullptr, 0.f, nullptr);
    // K7: out = x + gate * (cat @ lin2_w^T + lin2_b)   [4096 x 2048], K=10240
    gemm_tf32<0, 3><<<dim3(HH / BN, (BB * LL) / BM, 1), 256>>>(
        p_cat, HC2, 0, 0, lin2_w, HC2, 0, 0, out, HH, 0, 0,
        BB * LL, HH, HC2, 1, lin2_b, 0.f, x);
}

// round 3
// speedup vs baseline: 2.4028x; 2.4028x over previous
#include <cuda_runtime.h>
#include <cuda_fp16.h>
#include <cstdint>
#include <cstddef>

// ---------------------------------------------------------------------------
// SingleStreamBlock: B=2, L=2048, H=2048, NH=16, D=128, MLP=8192
// fp16 tensor-core implementation (mma.sync.m16n8k16 + ldmatrix + cp.async)
// ---------------------------------------------------------------------------
#define BB   2
#define LL   2048
#define HH   2048
#define NHH  16
#define DD   128
#define MLPD 8192
#define H3   6144          // 3*H
#define HC1  14336         // 3*H + MLP  (lin1 out cols)
#define HC2  10240         // H + MLP    (lin2 in cols)

// ------------------------- scratch (device globals) ------------------------
__device__ float  g_mod   [BB * H3];                        // shift|scale|gate (fp32)
__device__ __half g_xmodh [(size_t)BB * LL * HH];           // 16.8 MB
__device__ __half g_hh    [(size_t)BB * LL * HC1];          // 117 MB
__device__ __half g_qh    [(size_t)BB * NHH * LL * DD];     // 16.8 MB
__device__ __half g_kh    [(size_t)BB * NHH * LL * DD];     // 16.8 MB
__device__ __half g_logith[(size_t)BB * NHH * LL * LL];     // 268 MB
__device__ __half g_cath  [(size_t)BB * LL * HC2];          // 84 MB (attn|gelu)
__device__ __half g_w1h   [(size_t)HC1 * HH];               // 58 MB
__device__ __half g_w2h   [(size_t)HH * HC2];               // 42 MB

// ------------------------------ helpers ------------------------------------
__device__ __forceinline__ uint32_t smem_u32(const void* p) {
    uint32_t a;
    asm("{ .reg .u64 t; cvta.to.shared.u64 t, %1; cvt.u32.u64 %0, t; }"
        : "=r"(a) : "l"(p));
    return a;
}

__device__ __forceinline__ void cp16(uint32_t s, const void* g) {
    asm volatile("cp.async.cg.shared.global [%0], [%1], 16;" :: "r"(s), "l"(g));
}

__device__ __forceinline__ void ldsm4(uint32_t* r, uint32_t addr) {
    asm volatile("ldmatrix.sync.aligned.m8n8.x4.shared.b16 {%0,%1,%2,%3}, [%4];"
        : "=r"(r[0]), "=r"(r[1]), "=r"(r[2]), "=r"(r[3]) : "r"(addr));
}

__device__ __forceinline__ void ldsm4t(uint32_t* r, uint32_t addr) {
    asm volatile("ldmatrix.sync.aligned.m8n8.x4.trans.shared.b16 {%0,%1,%2,%3}, [%4];"
        : "=r"(r[0]), "=r"(r[1]), "=r"(r[2]), "=r"(r[3]) : "r"(addr));
}

__device__ __forceinline__ void mma16816(float* d, const uint32_t* a, const uint32_t* b) {
    asm volatile(
        "mma.sync.aligned.m16n8k16.row.col.f32.f16.f16.f32 "
        "{%0,%1,%2,%3}, {%4,%5,%6,%7}, {%8,%9}, {%0,%1,%2,%3};"
        : "+f"(d[0]), "+f"(d[1]), "+f"(d[2]), "+f"(d[3])
        : "r"(a[0]), "r"(a[1]), "r"(a[2]), "r"(a[3]), "r"(b[0]), "r"(b[1]));
}

// ========================= fp16 tensor-core GEMM ============================
// C[M,N] = A[M,K] @ op(B)  (A row-major [M][K])
// BLAY 0 (NT): B row-major [N][K]      BLAY 1 (NN): B row-major [K][N]
// EPI 0: C half = v            EPI 1: C half = v + bias[c]
// EPI 2: C half = v * scl      EPI 3: C fp32 = xres + gate*(v + bias[c])
#define HBM 128
#define HBN 128
#define HBK 64                       // halves (128 bytes per A/B-NT row)
#define HSTG 3
#define HA_BYTES (HBM * 128)         // 16384
#define HB_BYTES 16384               // NT: 128x128B, NN: 64x256B
#define HSTAGE (HA_BYTES + HB_BYTES) // 32768
#define HSMEM (HSTG * HSTAGE)        // 98304

template<int BLAY>
__device__ __forceinline__ void stage_load(uint32_t sbuf,
                                           const __half* __restrict__ A, int lda,
                                           const __half* __restrict__ B, int ldb,
                                           int m0, int n0, int kt, int tid) {
    const __half* Ab = A + (size_t)m0 * lda + kt * HBK;
#pragma unroll
    for (int i = 0; i < 4; i++) {
        int idx = tid + i * 256;
        int r = idx >> 3, c = idx & 7;
        cp16(sbuf + r * 128 + ((c << 4) ^ ((r & 7) << 4)),
             Ab + (size_t)r * lda + c * 8);
    }
    if (BLAY == 0) {
        const __half* Bb = B + (size_t)n0 * ldb + kt * HBK;
#pragma unroll
        for (int i = 0; i < 4; i++) {
            int idx = tid + i * 256;
            int r = idx >> 3, c = idx & 7;
            cp16(sbuf + HA_BYTES + r * 128 + ((c << 4) ^ ((r & 7) << 4)),
                 Bb + (size_t)r * ldb + c * 8);
        }
    } else {
        const __half* Bb = B + (size_t)(kt * HBK) * ldb + n0;
#pragma unroll
        for (int i = 0; i < 4; i++) {
            int idx = tid + i * 256;
            int r = idx >> 4, c = idx & 15;          // r: 0..63 (k), c: n-chunk
            cp16(sbuf + HA_BYTES + r * 256 + ((c ^ (r & 7)) << 4),
                 Bb + (size_t)r * ldb + c * 8);
        }
    }
}

template<int BLAY, int EPI>
__global__ __launch_bounds__(256, 1) void hgemm(
    const __half* __restrict__ Ag, int lda, long long Ao, long long Ai,
    const __half* __restrict__ Bg, int ldb, long long Bo, long long Bi,
    void* __restrict__ Cg, int ldc, long long Co, long long Ci,
    int K, int zdiv,
    const float* __restrict__ bias, float scl,
    const float* __restrict__ xres)
{
    extern __shared__ char smem_raw[];
    uint32_t sb = smem_u32(smem_raw);
    int tid = threadIdx.x, lane = tid & 31, w = tid >> 5;
    int wm = w >> 1, wn = w & 1;                 // 4x2 warps, warp tile 32x64

    int z = blockIdx.z;
    size_t zA = (size_t)(z / zdiv) * Ao + (size_t)(z % zdiv) * Ai;
    size_t zB = (size_t)(z / zdiv) * Bo + (size_t)(z % zdiv) * Bi;
    size_t zC = (size_t)(z / zdiv) * Co + (size_t)(z % zdiv) * Ci;
    const __half* A = Ag + zA;
    const __half* B = Bg + zB;

    int m0 = blockIdx.y * HBM;
    int n0 = blockIdx.x * HBN;
    int nkt = K / HBK;

    // ---- prologue ----
#pragma unroll
    for (int t = 0; t < HSTG - 1; t++) {
        if (t < nkt) {
            stage_load<BLAY>(sb + t * HSTAGE, A, lda, B, ldb, m0, n0, t, tid);
            asm volatile("cp.async.commit_group;" ::: "memory");
        }
    }

    float acc[2][8][4];
#pragma unroll
    for (int mi = 0; mi < 2; mi++)
#pragma unroll
        for (int ni = 0; ni < 8; ni++)
#pragma unroll
            for (int e = 0; e < 4; e++) acc[mi][ni][e] = 0.f;

    // ---- per-lane ldmatrix address components ----
    int l15 = lane & 15;
    uint32_t khi = (lane >> 4) << 4;             // +16B for hi half of x4
    uint32_t aoff[2], amask[2];
#pragma unroll
    for (int mi = 0; mi < 2; mi++) {
        int row = wm * 32 + mi * 16 + l15;
        aoff[mi]  = row * 128;
        amask[mi] = (row & 7) << 4;
    }
    uint32_t boff[4], bmask[4];
    if (BLAY == 0) {
#pragma unroll
        for (int p = 0; p < 4; p++) {
            int row = wn * 64 + p * 16 + l15;
            boff[p]  = HA_BYTES + row * 128;
            bmask[p] = (row & 7) << 4;
        }
    } else {
#pragma unroll
        for (int p = 0; p < 4; p++) {
            int nc = wn * 8 + p * 2 + (lane >> 4);
            boff[p] = HA_BYTES + l15 * 256 + (uint32_t)((nc ^ (lane & 7)) << 4);
        }
    }

    // ---- main loop ----
    for (int kt = 0; kt < nkt; kt++) {
        int pend = nkt - kt - 1;
        if (pend > HSTG - 2) pend = HSTG - 2;
        if (pend) asm volatile("cp.async.wait_group 1;" ::: "memory");
        else      asm volatile("cp.async.wait_group 0;" ::: "memory");
        __syncthreads();

        int tl = kt + HSTG - 1;
        if (tl < nkt) {
            stage_load<BLAY>(sb + (tl % HSTG) * HSTAGE, A, lda, B, ldb, m0, n0, tl, tid);
            asm volatile("cp.async.commit_group;" ::: "memory");
        }

        uint32_t sA = sb + (kt % HSTG) * HSTAGE;
#pragma unroll
        for (int ks = 0; ks < 4; ks++) {
            uint32_t kb = ks * 32 + khi;
            uint32_t a[2][4];
#pragma unroll
            for (int mi = 0; mi < 2; mi++)
                ldsm4(a[mi], sA + aoff[mi] + (kb ^ amask[mi]));

            uint32_t bf[8][2];
            if (BLAY == 0) {
#pragma unroll
                for (int p = 0; p < 4; p++) {
                    uint32_t r[4];
                    ldsm4(r, sA + boff[p] + (kb ^ bmask[p]));
                    bf[2 * p][0]     = r[0];
                    bf[2 * p + 1][0] = r[1];
                    bf[2 * p][1]     = r[2];
                    bf[2 * p + 1][1] = r[3];
                }
            } else {
#pragma unroll
                for (int p = 0; p < 4; p++) {
                    uint32_t r[4];
                    ldsm4t(r, sA + boff[p] + ks * 4096);
                    bf[2 * p][0]     = r[0];
                    bf[2 * p][1]     = r[1];
                    bf[2 * p + 1][0] = r[2];
                    bf[2 * p + 1][1] = r[3];
                }
            }
#pragma unroll
            for (int mi = 0; mi < 2; mi++)
#pragma unroll
                for (int ni = 0; ni < 8; ni++)
                    mma16816(acc[mi][ni], a[mi], bf[ni]);
        }
    }

    // ---- epilogue ----
    int rb = m0 + wm * 32, nb = n0 + wn * 64;
    int r0 = lane >> 2, c0 = (lane & 3) * 2;
    if (EPI == 3) {
        float* C = (float*)Cg + zC;
#pragma unroll
        for (int mi = 0; mi < 2; mi++) {
#pragma unroll
            for (int ni = 0; ni < 8; ni++) {
                int r = rb + mi * 16 + r0;
                int c = nb + ni * 8 + c0;
                int bt = r >> 11;
                float g0 = g_mod[bt * H3 + 2 * HH + c];
                float g1 = g_mod[bt * H3 + 2 * HH + c + 1];
                float b0 = bias[c], b1 = bias[c + 1];
                C[(size_t)r * ldc + c]       = xres[(size_t)r * ldc + c]       + g0 * (acc[mi][ni][0] + b0);
                C[(size_t)r * ldc + c + 1]   = xres[(size_t)r * ldc + c + 1]   + g1 * (acc[mi][ni][1] + b1);
                C[(size_t)(r + 8) * ldc + c]     = xres[(size_t)(r + 8) * ldc + c]     + g0 * (acc[mi][ni][2] + b0);
                C[(size_t)(r + 8) * ldc + c + 1] = xres[(size_t)(r + 8) * ldc + c + 1] + g1 * (acc[mi][ni][3] + b1);
            }
        }
    } else {
        __half* C = (__half*)Cg + zC;
#pragma unroll
        for (int mi = 0; mi < 2; mi++) {
#pragma unroll
            for (int ni = 0; ni < 8; ni++) {
                int r = rb + mi * 16 + r0;
                int c = nb + ni * 8 + c0;
                float v0 = acc[mi][ni][0], v1 = acc[mi][ni][1];
                float v2 = acc[mi][ni][2], v3 = acc[mi][ni][3];
                if (EPI == 1) {
                    float b0 = bias[c], b1 = bias[c + 1];
                    v0 += b0; v1 += b1; v2 += b0; v3 += b1;
                } else if (EPI == 2) {
                    v0 *= scl; v1 *= scl; v2 *= scl; v3 *= scl;
                }
                *(__half2*)(C + (size_t)r * ldc + c)       = __floats2half2_rn(v0, v1);
                *(__half2*)(C + (size_t)(r + 8) * ldc + c) = __floats2half2_rn(v2, v3);
            }
        }
    }
}

// ---------------------- weight fp32 -> fp16 convert -------------------------
__global__ void cvt_half_kernel(const float4* __restrict__ src,
                                __half2* __restrict__ dst, int n4) {
    int i = blockIdx.x * blockDim.x + threadIdx.x;
    if (i >= n4) return;
    float4 v = src[i];
    dst[2 * i]     = __floats2half2_rn(v.x, v.y);
    dst[2 * i + 1] = __floats2half2_rn(v.z, v.w);
}

// ------------------------- K0: mod = silu(vec) @ mod_w^T + mod_b ------------
__global__ void mod_gemm_kernel(const float* __restrict__ vec,
                                const float* __restrict__ mod_w,
                                const float* __restrict__ mod_b) {
    int w    = (blockIdx.x * blockDim.x + threadIdx.x) >> 5;
    int lane = threadIdx.x & 31;
    if (w >= BB * H3) return;
    int b = w / H3, j = w % H3;
    const float* vr = vec + (size_t)b * HH;
    const float* wr = mod_w + (size_t)j * HH;
    float acc = 0.f;
    for (int k = lane; k < HH; k += 32) {
        float v = vr[k];
        float s = v / (1.f + expf(-v));
        acc += s * wr[k];
    }
#pragma unroll
    for (int o = 16; o; o >>= 1) acc += __shfl_xor_sync(0xffffffffu, acc, o);
    if (lane == 0) g_mod[w] = acc + mod_b[j];
}

// ------------------ K1: x_mod = (1+scale)*LN(x) + shift  (fp16 out) ---------
__global__ void ln_mod_kernel(const float* __restrict__ x) {
    __shared__ float red[32];
    __shared__ float bval[2];
    int row = blockIdx.x;
    int tid = threadIdx.x;
    int lane = tid & 31, wid = tid >> 5;
    const float* xr = x + (size_t)row * HH;

    float v[8];
    float s = 0.f;
#pragma unroll
    for (int i = 0; i < 8; i++) { v[i] = xr[tid + i * 256]; s += v[i]; }
#pragma unroll
    for (int o = 16; o; o >>= 1) s += __shfl_xor_sync(0xffffffffu, s, o);
    if (lane == 0) red[wid] = s;
    __syncthreads();
    if (tid < 32) {
        float r = (tid < 8) ? red[tid] : 0.f;
#pragma unroll
        for (int o = 4; o; o >>= 1) r += __shfl_xor_sync(0xffffffffu, r, o);
        if (tid == 0) bval[0] = r;
    }
    __syncthreads();
    float mu = bval[0] * (1.f / HH);

    float sq = 0.f;
#pragma unroll
    for (int i = 0; i < 8; i++) { float d = v[i] - mu; sq += d * d; }
#pragma unroll
    for (int o = 16; o; o >>= 1) sq += __shfl_xor_sync(0xffffffffu, sq, o);
    __syncthreads();
    if (lane == 0) red[wid] = sq;
    __syncthreads();
    if (tid < 32) {
        float r = (tid < 8) ? red[tid] : 0.f;
#pragma unroll
        for (int o = 4; o; o >>= 1) r += __shfl_xor_sync(0xffffffffu, r, o);
        if (tid == 0) bval[1] = r;
    }
    __syncthreads();
    float rstd = rsqrtf(bval[1] * (1.f / HH) + 1e-6f);

    int b = row >> 11;
#pragma unroll
    for (int i = 0; i < 8; i++) {
        int c = tid + i * 256;
        float sc = g_mod[b * H3 + HH + c];
        float sh = g_mod[b * H3 + c];
        g_xmodh[(size_t)row * HH + c] =
            __float2half((1.f + sc) * ((v[i] - mu) * rstd) + sh);
    }
}

// ----------------- K3: q/k rmsnorm + rope -> g_qh, g_kh ---------------------
__global__ void qkprep_kernel(const float* __restrict__ pe,
                              const float* __restrict__ qsc,
                              const float* __restrict__ ksc) {
    int sel  = blockIdx.y;                                   // 0=q, 1=k
    int gw   = blockIdx.x * (blockDim.x >> 5) + (threadIdx.x >> 5);
    int lane = threadIdx.x & 31;
    int b   = gw >> 15;
    int rem = gw & 32767;
    int n   = rem >> 11;
    int l   = rem & 2047;

    const __half* src = g_hh + (size_t)(b * LL + l) * HC1 + sel * HH + n * DD + lane * 4;
    uint2 raw = *(const uint2*)src;
    float2 f0 = __half22float2(*(__half2*)&raw.x);
    float2 f1 = __half22float2(*(__half2*)&raw.y);
    const float* scp = sel ? ksc : qsc;
    float4 sv = *(const float4*)(scp + lane * 4);

    float ss = f0.x * f0.x + f0.y * f0.y + f1.x * f1.x + f1.y * f1.y;
#pragma unroll
    for (int o = 16; o; o >>= 1) ss += __shfl_xor_sync(0xffffffffu, ss, o);
    float r = rsqrtf(ss * (1.f / DD) + 1e-6f);

    float tx = f0.x * r * sv.x, ty = f0.y * r * sv.y;
    float tz = f1.x * r * sv.z, tw = f1.y * r * sv.w;

    const float* peb = pe + ((size_t)(b * LL + l) * (DD / 2) + lane * 2) * 4;
    float4 p0 = *(const float4*)(peb);
    float4 p1 = *(const float4*)(peb + 4);
    float o0 = p0.x * tx + p0.y * ty;
    float o1 = p0.z * tx + p0.w * ty;
    float o2 = p1.x * tz + p1.y * tw;
    float o3 = p1.z * tz + p1.w * tw;

    __half* dst = (sel ? g_kh : g_qh) + ((size_t)(b * NHH + n) * LL + l) * DD + lane * 4;
    uint2 o;
    *(__half2*)&o.x = __floats2half2_rn(o0, o1);
    *(__half2*)&o.y = __floats2half2_rn(o2, o3);
    *(uint2*)dst = o;
}

// ---------------- K3b: g_cath[:,H:] = gelu(g_hh[:,3H:]) ---------------------
__global__ void gelu_kernel() {
    size_t i = (size_t)blockIdx.x * blockDim.x + threadIdx.x;  // half2 index
    size_t m = i >> 12;          // / 4096 half2 per row
    size_t j = i & 4095;
    float2 f = __half22float2(*(__half2*)(g_hh + m * HC1 + H3 + 2 * j));
    float t0 = 0.7978845608028654f * (f.x + 0.044715f * f.x * f.x * f.x);
    float t1 = 0.7978845608028654f * (f.y + 0.044715f * f.y * f.y * f.y);
    float r0 = 0.5f * f.x * (1.f + tanhf(t0));
    float r1 = 0.5f * f.y * (1.f + tanhf(t1));
    *(__half2*)(g_cath + m * HC2 + HH + 2 * j) = __floats2half2_rn(r0, r1);
}

// ---------------------- K5: row softmax over g_logith -----------------------
__global__ void softmax_kernel() {
    __shared__ float red[32];
    __shared__ float bval;
    size_t row = blockIdx.x;
    __half2* p = (__half2*)(g_logith + row * LL);
    int tid = threadIdx.x, lane = tid & 31, wid = tid >> 5;

    float2 v[4];
    float mx = -1e30f;
#pragma unroll
    for (int i = 0; i < 4; i++) {
        v[i] = __half22float2(p[tid + i * 256]);
        mx = fmaxf(mx, fmaxf(v[i].x, v[i].y));
    }
#pragma unroll
    for (int o = 16; o; o >>= 1) mx = fmaxf(mx, __shfl_xor_sync(0xffffffffu, mx, o));
    if (lane == 0) red[wid] = mx;
    __syncthreads();
    if (tid < 32) {
        float r = (tid < 8) ? red[tid] : -1e30f;
#pragma unroll
        for (int o = 4; o; o >>= 1) r = fmaxf(r, __shfl_xor_sync(0xffffffffu, r, o));
        if (tid == 0) bval = r;
    }
    __syncthreads();
    mx = bval;

    float s = 0.f;
#pragma unroll
    for (int i = 0; i < 4; i++) {
        v[i].x = expf(v[i].x - mx);
        v[i].y = expf(v[i].y - mx);
        s += v[i].x + v[i].y;
    }
#pragma unroll
    for (int o = 16; o; o >>= 1) s += __shfl_xor_sync(0xffffffffu, s, o);
    __syncthreads();
    if (lane == 0) red[wid] = s;
    __syncthreads();
    if (tid < 32) {
        float r = (tid < 8) ? red[tid] : 0.f;
#pragma unroll
        for (int o = 4; o; o >>= 1) r += __shfl_xor_sync(0xffffffffu, r, o);
        if (tid == 0) bval = r;
    }
    __syncthreads();
    float inv = 1.f / bval;
#pragma unroll
    for (int i = 0; i < 4; i++)
        p[tid + i * 256] = __floats2half2_rn(v[i].x * inv, v[i].y * inv);
}

// ---------------------------------------------------------------------------
extern "C" void kernel_launch(void* const* d_in, const int* in_sizes, int n_in,
                              void* d_out, int out_size) {
    const float* x       = (const float*)d_in[0];
    const float* vec     = (const float*)d_in[1];
    const float* pe      = (const float*)d_in[2];
    const float* mod_w   = (const float*)d_in[3];
    const float* mod_b   = (const float*)d_in[4];
    const float* lin1_w  = (const float*)d_in[5];
    const float* lin1_b  = (const float*)d_in[6];
    const float* lin2_w  = (const float*)d_in[7];
    const float* lin2_b  = (const float*)d_in[8];
    const float* q_scale = (const float*)d_in[9];
    const float* k_scale = (const float*)d_in[10];
    float* out = (float*)d_out;

    void* tmp;
    cudaGetSymbolAddress(&tmp, g_xmodh);  __half* p_xmod = (__half*)tmp;
    cudaGetSymbolAddress(&tmp, g_hh);     __half* p_h    = (__half*)tmp;
    cudaGetSymbolAddress(&tmp, g_qh);     __half* p_q    = (__half*)tmp;
    cudaGetSymbolAddress(&tmp, g_kh);     __half* p_k    = (__half*)tmp;
    cudaGetSymbolAddress(&tmp, g_logith); __half* p_lg   = (__half*)tmp;
    cudaGetSymbolAddress(&tmp, g_cath);   __half* p_cat  = (__half*)tmp;
    cudaGetSymbolAddress(&tmp, g_w1h);    __half* p_w1   = (__half*)tmp;
    cudaGetSymbolAddress(&tmp, g_w2h);    __half* p_w2   = (__half*)tmp;

    static int attr_set = 0;
    if (!attr_set) {
        cudaFuncSetAttribute(hgemm<0, 1>, cudaFuncAttributeMaxDynamicSharedMemorySize, HSMEM);
        cudaFuncSetAttribute(hgemm<0, 2>, cudaFuncAttributeMaxDynamicSharedMemorySize, HSMEM);
        cudaFuncSetAttribute(hgemm<1, 0>, cudaFuncAttributeMaxDynamicSharedMemorySize, HSMEM);
        cudaFuncSetAttribute(hgemm<0, 3>, cudaFuncAttributeMaxDynamicSharedMemorySize, HSMEM);
        attr_set = 1;
    }

    // weight conversions (fp32 -> fp16)
    cvt_half_kernel<<<(HC1 * HH / 4 + 255) / 256, 256>>>(
        (const float4*)lin1_w, (__half2*)p_w1, HC1 * HH / 4);
    cvt_half_kernel<<<(HH * HC2 / 4 + 255) / 256, 256>>>(
        (const float4*)lin2_w, (__half2*)p_w2, HH * HC2 / 4);

    // K0: modulation vectors
    mod_gemm_kernel<<<(BB * H3) / 8, 256>>>(vec, mod_w, mod_b);
    // K1: layernorm + modulate -> fp16
    ln_mod_kernel<<<BB * LL, 256>>>(x);
    // K2: h = x_mod @ lin1_w^T + lin1_b   [4096 x 14336], K=2048
    hgemm<0, 1><<<dim3(HC1 / HBN, (BB * LL) / HBM, 1), 256, HSMEM>>>(
        p_xmod, HH, 0, 0, p_w1, HH, 0, 0, p_h, HC1, 0, 0,
        HH, 1, lin1_b, 0.f, nullptr);
    // K3: q/k rmsnorm + rope
    qkprep_kernel<<<dim3((BB * NHH * LL) / 8, 2, 1), 256>>>(pe, q_scale, k_scale);
    // K3b: gelu(mlp) -> g_cath right half
    gelu_kernel<<<(unsigned)(((size_t)BB * LL * MLPD / 2) / 256), 256>>>();
    // K4: logits = q @ k^T / sqrt(D)   z = B*NH, [2048 x 2048], K=128
    hgemm<0, 2><<<dim3(LL / HBN, LL / HBM, BB * NHH), 256, HSMEM>>>(
        p_q, DD, (long long)LL * DD, 0,
        p_k, DD, (long long)LL * DD, 0,
        p_lg, LL, (long long)LL * LL, 0,
        DD, 1, nullptr, 0.08838834764831845f, nullptr);
    // K5: softmax rows
    softmax_kernel<<<BB * NHH * LL, 256>>>();
    // K6: attn = P @ V   z = B*NH, [2048 x 128], K=2048  (V strided in g_hh, NN)
    hgemm<1, 0><<<dim3(1, LL / HBM, BB * NHH), 256, HSMEM>>>(
        p_lg, LL, (long long)NHH * LL * LL, (long long)LL * LL,
        p_h + 2 * HH, HC1, (long long)LL * HC1, (long long)DD,
        p_cat, HC2, (long long)LL * HC2, (long long)DD,
        LL, NHH, nullptr, 0.f, nullptr);
    // K7: out = x + gate * (cat @ lin2_w^T + lin2_b)   [4096 x 2048], K=10240
    hgemm<0, 3><<<dim3(HH / HBN, (BB * LL) / HBM, 1), 256, HSMEM>>>(
        p_cat, HC2, 0, 0, p_w2, HC2, 0, 0, out, HH, 0, 0,
        HC2, 1, lin2_b, 0.f, x);
}